// round 15
// baseline (speedup 1.0000x reference)
#include <cuda_runtime.h>
#include <cuda_fp16.h>
#include <cstdint>

// ---------------------------------------------------------------------------
// Fused LayerNorm-LSTM cell, sm_100 legacy tensor path.
//   Kernel 0: convert x,h -> g_A, Wih,Whh -> g_W (fp16, k-permuted).
//   Kernel 1: v = A @ W^T via mma.sync.m16n8k16.f16 -> g_V f32.
//             128x64 tiles (2048 CTAs -> 6.92 waves, 99% util), 32x32 warp
//             tiles, NS=3, 2 CTAs/SM.
//   Kernel 2: 4x LN + LSTM + LN -> out; 128 thr/block, 8 elem/thread.
// ---------------------------------------------------------------------------

#define BM 128
#define BN 64
#define BKH 64                          // k halfs per stage (128 B per row)
#define NS 3
#define NT 32                           // 2048 / 64
#define A_BYTES (BM * 128)              // 16384
#define STAGE_BYTES ((BM + BN) * 128)   // 24576
#define SMEM_SZ (NS * STAGE_BYTES + 1024)   // 74752

__device__ float  g_V[4096u * 4096u];   // 64 MB pre-LN gate activations
__device__ __half g_A[4096u * 2048u];   // 16 MB fp16 [x|h], k-permuted
__device__ __half g_W[4096u * 2048u];   // 16 MB fp16 [Wih|Whh], k-permuted

// ---- helpers ---------------------------------------------------------------

__device__ __forceinline__ uint32_t s2u(const void* p) {
    return (uint32_t)__cvta_generic_to_shared(p);
}
__device__ __forceinline__ void cp_async16(uint32_t dst, const void* src) {
    asm volatile("cp.async.cg.shared.global [%0], [%1], 16;\n" :: "r"(dst), "l"(src));
}
__device__ __forceinline__ void cp_commit() {
    asm volatile("cp.async.commit_group;\n" ::: "memory");
}
template <int N> __device__ __forceinline__ void cp_wait() {
    asm volatile("cp.async.wait_group %0;\n" :: "n"(N) : "memory");
}
__device__ __forceinline__ void lds128(uint32_t* v, uint32_t a) {
    asm volatile("ld.shared.v4.b32 {%0,%1,%2,%3}, [%4];"
                 : "=r"(v[0]), "=r"(v[1]), "=r"(v[2]), "=r"(v[3]) : "r"(a));
}
__device__ __forceinline__ void mma_f16(float* d, uint32_t a0, uint32_t a1,
                                        uint32_t a2, uint32_t a3,
                                        uint32_t b0, uint32_t b1) {
    asm volatile(
        "mma.sync.aligned.m16n8k16.row.col.f32.f16.f16.f32 "
        "{%0,%1,%2,%3}, {%4,%5,%6,%7}, {%8,%9}, {%0,%1,%2,%3};\n"
        : "+f"(d[0]), "+f"(d[1]), "+f"(d[2]), "+f"(d[3])
        : "r"(a0), "r"(a1), "r"(a2), "r"(a3), "r"(b0), "r"(b1));
}

// ---- Kernel 0: fp16 convert + k-permute, 1 thread per 16B output -----------

__global__ __launch_bounds__(256)
void tohalf(const float* __restrict__ x, const float* __restrict__ h,
            const float* __restrict__ Wih, const float* __restrict__ Whh) {
    const uint32_t q = blockIdx.x * 256u + threadIdx.x;     // 0 .. 2M-1
    const uint32_t tensor = q >> 20;                        // 0=A, 1=W
    const uint32_t r = q & 0xFFFFFu;
    const uint32_t blk = r >> 2;
    const uint32_t i = r & 3u;
    const uint32_t row = blk >> 6;
    const uint32_t chunk = blk & 63u;

    const float* src;
    __half* dst;
    if (tensor == 0) {
        src = (chunk < 32u) ? x + (size_t)row * 1024 + chunk * 32
                            : h + (size_t)row * 1024 + (chunk - 32u) * 32;
        dst = g_A + (size_t)row * 2048 + chunk * 32;
    } else {
        src = (chunk < 32u) ? Wih + (size_t)row * 1024 + chunk * 32
                            : Whh + (size_t)row * 1024 + (chunk - 32u) * 32;
        dst = g_W + (size_t)row * 2048 + chunk * 32;
    }

    const float2* p = (const float2*)src + i;
    float2 a = p[0], b = p[4], c2 = p[8], d = p[12];
    union { __half2 h2[4]; uint4 u; } o;
    o.h2[0] = __float22half2_rn(a);
    o.h2[1] = __float22half2_rn(b);
    o.h2[2] = __float22half2_rn(c2);
    o.h2[3] = __float22half2_rn(d);
    ((uint4*)dst)[i] = o.u;
}

// ---- Kernel 1: fp16 GEMM, 128x64 tile, 2 CTAs/SM ----------------------------
// Per stage: 128 A rows then 64 B rows, 128 B each; per-row parity XOR on
// 16B granules keeps every lds.128 phase conflict-free (consumer rows all
// share parity g&1).

__global__ __launch_bounds__(256, 2)
void gemm_f16(const __half* __restrict__ gA, const __half* __restrict__ gW) {
    extern __shared__ float dsm[];
    const uint32_t dyn0 = s2u(dsm);
    const uint32_t base = (dyn0 + 1023u) & ~1023u;

    const int tid  = threadIdx.x;
    const int warp = tid >> 5;
    const int lane = tid & 31;
    const int g    = lane >> 2;               // 0..7
    const int t4   = lane & 3;                // 0..3
    const int wm = (warp & 3) * 32;           // 4 x 2 warp grid, 32x32 warp tile
    const int wn = (warp >> 2) * 32;
    const int bm0 = blockIdx.y * BM;
    const int bn0 = blockIdx.x * BN;
    const uint32_t gpar = (uint32_t)(g & 1);

    float acc[2][4][4];
    #pragma unroll
    for (int i = 0; i < 2; i++)
        #pragma unroll
        for (int j = 0; j < 4; j++)
            #pragma unroll
            for (int k = 0; k < 4; k++) acc[i][j][k] = 0.f;

    // loaders: A 2 thr/row x 4 chunks; B 4 thr/row x 2 chunks
    const int lrowA = tid >> 1;               // 0..127
    const int ac0   = (tid & 1) * 4;
    const uint32_t swA = (uint32_t)(lrowA & 1) << 2;
    const int lrowB = tid >> 2;               // 0..63
    const int bc0   = (tid & 3) * 2;
    const uint32_t swB = (uint32_t)(lrowB & 1) << 2;

    auto issue_loads = [&](int kt) {
        const uint32_t sb = base + (uint32_t)(kt % NS) * STAGE_BYTES;
        const __half* arow = gA + (size_t)(bm0 + lrowA) * 2048 + kt * BKH;
        #pragma unroll
        for (int j = 0; j < 4; j++) {
            int c = ac0 + j;
            cp_async16(sb + (uint32_t)lrowA * 128u + ((uint32_t)c ^ swA) * 16u,
                       arow + c * 8);
        }
        const __half* brow = gW + (size_t)(bn0 + lrowB) * 2048 + kt * BKH;
        #pragma unroll
        for (int j = 0; j < 2; j++) {
            int c = bc0 + j;
            cp_async16(sb + A_BYTES + (uint32_t)lrowB * 128u + ((uint32_t)c ^ swB) * 16u,
                       brow + c * 8);
        }
        cp_commit();
    };

    issue_loads(0); issue_loads(1);

    for (int kt = 0; kt < NT; kt++) {
        if (kt < NT - 1) cp_wait<1>();
        else             cp_wait<0>();
        __syncthreads();

        if (kt + NS - 1 < NT) issue_loads(kt + NS - 1);

        const uint32_t sA = base + (uint32_t)(kt % NS) * STAGE_BYTES;
        const uint32_t sB = sA + A_BYTES;
        const uint32_t tof = (uint32_t)t4 * 16u;

        #pragma unroll
        for (int i = 0; i < 2; i++) {                     // 32-half sub-blocks
            const uint32_t ie = ((uint32_t)i ^ gpar) * 64u;

            uint32_t B[4][4];
            #pragma unroll
            for (int nt = 0; nt < 4; nt++)
                lds128(B[nt], sB + (uint32_t)(wn + nt * 8 + g) * 128u + ie + tof);

            uint32_t A0[2][4], A8[2][4];
            #pragma unroll
            for (int mt = 0; mt < 2; mt++) {
                uint32_t ad = sA + (uint32_t)(wm + mt * 16 + g) * 128u + ie + tof;
                lds128(A0[mt], ad);
                lds128(A8[mt], ad + 8 * 128);
            }
            #pragma unroll
            for (int s = 0; s < 2; s++)                   // two k16 steps
                #pragma unroll
                for (int mt = 0; mt < 2; mt++)
                    #pragma unroll
                    for (int nt = 0; nt < 4; nt++)
                        mma_f16(acc[mt][nt],
                                A0[mt][2 * s], A8[mt][2 * s],
                                A0[mt][2 * s + 1], A8[mt][2 * s + 1],
                                B[nt][2 * s], B[nt][2 * s + 1]);
        }
    }

    // epilogue: direct STG of fragments
    #pragma unroll
    for (int mt = 0; mt < 2; mt++) {
        #pragma unroll
        for (int nt = 0; nt < 4; nt++) {
            int m = bm0 + wm + mt * 16 + g;
            int n = bn0 + wn + nt * 8 + t4 * 2;
            *(float2*)&g_V[(size_t)m * 4096 + n]       = make_float2(acc[mt][nt][0], acc[mt][nt][1]);
            *(float2*)&g_V[(size_t)(m + 8) * 4096 + n] = make_float2(acc[mt][nt][2], acc[mt][nt][3]);
        }
    }
}

// ---- Kernel 2: LN + LSTM + LN, 128 threads x 8 elems ------------------------

__device__ __forceinline__ float sigm(float v) {
    return __fdividef(1.f, 1.f + __expf(-v));
}
__device__ __forceinline__ float tanh_f(float v) {
    return fmaf(2.f, sigm(2.f * v), -1.f);
}
__device__ __forceinline__ float sum4(float4 v) { return v.x + v.y + v.z + v.w; }
__device__ __forceinline__ float sq4(float4 v) {
    return v.x * v.x + v.y * v.y + v.z * v.z + v.w * v.w;
}

__global__ __launch_bounds__(128)
void ln_lstm(const float* __restrict__ c,
             const float* __restrict__ b_ih,
             const float* __restrict__ gamma_ifgo, const float* __restrict__ beta_ifgo,
             const float* __restrict__ gamma_c,    const float* __restrict__ beta_c,
             float* __restrict__ out) {
    __shared__ float red[4][8];
    __shared__ float red2[4][2];

    const int b   = blockIdx.x;
    const int tid = threadIdx.x;            // 0..127; owns 8 H-elems
    const int w   = tid >> 5;

    const float4* vb   = (const float4*)(g_V + (size_t)b * 4096);
    const float4* bih4 = (const float4*)b_ih;

    float4 wv[4][2];
    float  s[4], ss[4];
    #pragma unroll
    for (int g = 0; g < 4; g++) {
        float4 t0 = vb[g * 256 + tid * 2];
        float4 t1 = vb[g * 256 + tid * 2 + 1];
        float4 b0 = bih4[g * 256 + tid * 2];
        float4 b1 = bih4[g * 256 + tid * 2 + 1];
        t0.x += b0.x; t0.y += b0.y; t0.z += b0.z; t0.w += b0.w;
        t1.x += b1.x; t1.y += b1.y; t1.z += b1.z; t1.w += b1.w;
        wv[g][0] = t0; wv[g][1] = t1;
        s[g]  = sum4(t0) + sum4(t1);
        ss[g] = sq4(t0) + sq4(t1);
    }
    #pragma unroll
    for (int o = 16; o > 0; o >>= 1) {
        #pragma unroll
        for (int g = 0; g < 4; g++) {
            s[g]  += __shfl_xor_sync(0xffffffffu, s[g],  o);
            ss[g] += __shfl_xor_sync(0xffffffffu, ss[g], o);
        }
    }
    if ((tid & 31) == 0) {
        #pragma unroll
        for (int g = 0; g < 4; g++) { red[w][g * 2] = s[g]; red[w][g * 2 + 1] = ss[g]; }
    }
    __syncthreads();

    float4 gate[4][2];
    #pragma unroll
    for (int g = 0; g < 4; g++) {
        float S  = red[0][g * 2]     + red[1][g * 2]     + red[2][g * 2]     + red[3][g * 2];
        float SS = red[0][g * 2 + 1] + red[1][g * 2 + 1] + red[2][g * 2 + 1] + red[3][g * 2 + 1];
        float mean = S * (1.f / 1024.f);
        float var  = fmaxf(SS - S * mean, 0.f) * (1.f / 1023.f);
        float inv  = 1.f / (sqrtf(var) + 1e-6f);
        #pragma unroll
        for (int q = 0; q < 2; q++) {
            float4 ga = ((const float4*)gamma_ifgo)[g * 256 + tid * 2 + q];
            float4 be = ((const float4*)beta_ifgo)[g * 256 + tid * 2 + q];
            float4 t  = wv[g][q];
            gate[g][q].x = ga.x * (t.x - mean) * inv + be.x;
            gate[g][q].y = ga.y * (t.y - mean) * inv + be.y;
            gate[g][q].z = ga.z * (t.z - mean) * inv + be.z;
            gate[g][q].w = ga.w * (t.w - mean) * inv + be.w;
        }
    }

    float4 cc[2];
    float s2 = 0.f, ss2 = 0.f;
    #pragma unroll
    for (int q = 0; q < 2; q++) {
        float4 ci = ((const float4*)(c + (size_t)b * 1024))[tid * 2 + q];
        float4 v;
        v.x = ci.x * sigm(gate[1][q].x + 1.f) + sigm(gate[0][q].x) * tanh_f(gate[2][q].x);
        v.y = ci.y * sigm(gate[1][q].y + 1.f) + sigm(gate[0][q].y) * tanh_f(gate[2][q].y);
        v.z = ci.z * sigm(gate[1][q].z + 1.f) + sigm(gate[0][q].z) * tanh_f(gate[2][q].z);
        v.w = ci.w * sigm(gate[1][q].w + 1.f) + sigm(gate[0][q].w) * tanh_f(gate[2][q].w);
        cc[q] = v;
        s2  += sum4(v);
        ss2 += sq4(v);
    }
    #pragma unroll
    for (int o = 16; o > 0; o >>= 1) {
        s2  += __shfl_xor_sync(0xffffffffu, s2,  o);
        ss2 += __shfl_xor_sync(0xffffffffu, ss2, o);
    }
    if ((tid & 31) == 0) { red2[w][0] = s2; red2[w][1] = ss2; }
    __syncthreads();
    float S  = red2[0][0] + red2[1][0] + red2[2][0] + red2[3][0];
    float SS = red2[0][1] + red2[1][1] + red2[2][1] + red2[3][1];
    float mean = S * (1.f / 1024.f);
    float var  = fmaxf(SS - S * mean, 0.f) * (1.f / 1023.f);
    float inv  = 1.f / (sqrtf(var) + 1e-6f);

    #pragma unroll
    for (int q = 0; q < 2; q++) {
        float4 gc = ((const float4*)gamma_c)[tid * 2 + q];
        float4 bc = ((const float4*)beta_c)[tid * 2 + q];
        float4 nc, nh;
        nc.x = gc.x * (cc[q].x - mean) * inv + bc.x;  nh.x = tanh_f(nc.x) * sigm(gate[3][q].x);
        nc.y = gc.y * (cc[q].y - mean) * inv + bc.y;  nh.y = tanh_f(nc.y) * sigm(gate[3][q].y);
        nc.z = gc.z * (cc[q].z - mean) * inv + bc.z;  nh.z = tanh_f(nc.z) * sigm(gate[3][q].z);
        nc.w = gc.w * (cc[q].w - mean) * inv + bc.w;  nh.w = tanh_f(nc.w) * sigm(gate[3][q].w);
        ((float4*)out)[(size_t)b * 256 + tid * 2 + q]                      = nh;
        ((float4*)out)[(size_t)4096 * 256 + (size_t)b * 256 + tid * 2 + q] = nc;
    }
}

// ---- launch ----------------------------------------------------------------

extern "C" void kernel_launch(void* const* d_in, const int* in_sizes, int n_in,
                              void* d_out, int out_size) {
    const float* x     = (const float*)d_in[0];
    const float* h     = (const float*)d_in[1];
    const float* c     = (const float*)d_in[2];
    const float* Wih   = (const float*)d_in[3];
    const float* bih   = (const float*)d_in[4];
    const float* Whh   = (const float*)d_in[5];
    const float* gifgo = (const float*)d_in[6];
    const float* bifgo = (const float*)d_in[7];
    const float* gc    = (const float*)d_in[8];
    const float* bc    = (const float*)d_in[9];
    float* out = (float*)d_out;

    __half *gA, *gW;
    cudaGetSymbolAddress((void**)&gA, g_A);
    cudaGetSymbolAddress((void**)&gW, g_W);

    cudaFuncSetAttribute(gemm_f16, cudaFuncAttributeMaxDynamicSharedMemorySize, SMEM_SZ);

    tohalf<<<8192, 256>>>(x, h, Wih, Whh);
    dim3 grid(4096 / BN, 4096 / BM);            // 64 x 32 = 2048 CTAs
    gemm_f16<<<grid, 256, SMEM_SZ>>>(gA, gW);
    ln_lstm<<<4096, 128>>>(c, bih, gifgo, bifgo, gc, bc, out);
}

// round 16
// speedup vs baseline: 1.0414x; 1.0414x over previous
#include <cuda_runtime.h>
#include <cuda_fp16.h>
#include <cstdint>

// ---------------------------------------------------------------------------
// Fused LayerNorm-LSTM cell, sm_100 legacy tensor path.
//   Kernel 0: convert x,h -> g_A, Wih,Whh -> g_W (fp16, k-permuted).
//   Kernel 1: v = A @ W^T via mma.sync.m16n8k16.f16 -> g_V f32 (R14 exact).
//   Kernel 2: persistent LN+LSTM+LN: 296 blocks x 128 thr, params in smem,
//             next-row prefetch into registers.
// ---------------------------------------------------------------------------

#define BM 128
#define BN 128
#define BKH 64                          // k halfs per stage (128 B per row)
#define NS 3
#define NT 32                           // 2048 / 64
#define A_BYTES (BM * 128)              // 16384
#define STAGE_BYTES ((BM + BN) * 128)   // 32768
#define SMEM_SZ (NS * STAGE_BYTES + 1024)   // 99328

#define LN_BLOCKS 296
#define LN_SMEM (14336 * 4)             // 57344 B of parameters

__device__ float  g_V[4096u * 4096u];   // 64 MB pre-LN gate activations
__device__ __half g_A[4096u * 2048u];   // 16 MB fp16 [x|h], k-permuted
__device__ __half g_W[4096u * 2048u];   // 16 MB fp16 [Wih|Whh], k-permuted

// ---- helpers ---------------------------------------------------------------

__device__ __forceinline__ uint32_t s2u(const void* p) {
    return (uint32_t)__cvta_generic_to_shared(p);
}
__device__ __forceinline__ void cp_async16(uint32_t dst, const void* src) {
    asm volatile("cp.async.cg.shared.global [%0], [%1], 16;\n" :: "r"(dst), "l"(src));
}
__device__ __forceinline__ void cp_commit() {
    asm volatile("cp.async.commit_group;\n" ::: "memory");
}
template <int N> __device__ __forceinline__ void cp_wait() {
    asm volatile("cp.async.wait_group %0;\n" :: "n"(N) : "memory");
}
__device__ __forceinline__ void lds128(uint32_t* v, uint32_t a) {
    asm volatile("ld.shared.v4.b32 {%0,%1,%2,%3}, [%4];"
                 : "=r"(v[0]), "=r"(v[1]), "=r"(v[2]), "=r"(v[3]) : "r"(a));
}
__device__ __forceinline__ void mma_f16(float* d, uint32_t a0, uint32_t a1,
                                        uint32_t a2, uint32_t a3,
                                        uint32_t b0, uint32_t b1) {
    asm volatile(
        "mma.sync.aligned.m16n8k16.row.col.f32.f16.f16.f32 "
        "{%0,%1,%2,%3}, {%4,%5,%6,%7}, {%8,%9}, {%0,%1,%2,%3};\n"
        : "+f"(d[0]), "+f"(d[1]), "+f"(d[2]), "+f"(d[3])
        : "r"(a0), "r"(a1), "r"(a2), "r"(a3), "r"(b0), "r"(b1));
}

// ---- Kernel 0: fp16 convert + k-permute, 1 thread per 16B output -----------

__global__ __launch_bounds__(256)
void tohalf(const float* __restrict__ x, const float* __restrict__ h,
            const float* __restrict__ Wih, const float* __restrict__ Whh) {
    const uint32_t q = blockIdx.x * 256u + threadIdx.x;     // 0 .. 2M-1
    const uint32_t tensor = q >> 20;                        // 0=A, 1=W
    const uint32_t r = q & 0xFFFFFu;
    const uint32_t blk = r >> 2;
    const uint32_t i = r & 3u;
    const uint32_t row = blk >> 6;
    const uint32_t chunk = blk & 63u;

    const float* src;
    __half* dst;
    if (tensor == 0) {
        src = (chunk < 32u) ? x + (size_t)row * 1024 + chunk * 32
                            : h + (size_t)row * 1024 + (chunk - 32u) * 32;
        dst = g_A + (size_t)row * 2048 + chunk * 32;
    } else {
        src = (chunk < 32u) ? Wih + (size_t)row * 1024 + chunk * 32
                            : Whh + (size_t)row * 1024 + (chunk - 32u) * 32;
        dst = g_W + (size_t)row * 2048 + chunk * 32;
    }

    const float2* p = (const float2*)src + i;
    float2 a = p[0], b = p[4], c2 = p[8], d = p[12];
    union { __half2 h2[4]; uint4 u; } o;
    o.h2[0] = __float22half2_rn(a);
    o.h2[1] = __float22half2_rn(b);
    o.h2[2] = __float22half2_rn(c2);
    o.h2[3] = __float22half2_rn(d);
    ((uint4*)dst)[i] = o.u;
}

// ---- Kernel 1: fp16 GEMM, 128x128 tile, 2 CTAs/SM (R14 exact) ---------------

__global__ __launch_bounds__(256, 2)
void gemm_f16(const __half* __restrict__ gA, const __half* __restrict__ gW) {
    extern __shared__ float dsm[];
    const uint32_t dyn0 = s2u(dsm);
    const uint32_t base = (dyn0 + 1023u) & ~1023u;

    const int tid  = threadIdx.x;
    const int warp = tid >> 5;
    const int lane = tid & 31;
    const int g    = lane >> 2;               // 0..7
    const int t4   = lane & 3;                // 0..3
    const int wm = (warp & 1) * 64;           // 64x32 warp tile
    const int wn = (warp >> 1) * 32;
    const int bm0 = blockIdx.y * BM;
    const int bn0 = blockIdx.x * BN;
    const uint32_t gpar = (uint32_t)(g & 1);

    float acc[4][4][4];
    #pragma unroll
    for (int i = 0; i < 4; i++)
        #pragma unroll
        for (int j = 0; j < 4; j++)
            #pragma unroll
            for (int k = 0; k < 4; k++) acc[i][j][k] = 0.f;

    const int lrow = tid >> 1;
    const int lc0  = (tid & 1) * 4;
    const uint32_t lsw = (uint32_t)(lrow & 1) << 2;

    auto issue_loads = [&](int kt) {
        const uint32_t sb = base + (uint32_t)(kt % NS) * STAGE_BYTES;
        const __half* arow = gA + (size_t)(bm0 + lrow) * 2048 + kt * BKH;
        const __half* brow = gW + (size_t)(bn0 + lrow) * 2048 + kt * BKH;
        #pragma unroll
        for (int j = 0; j < 4; j++) {
            int c = lc0 + j;
            uint32_t coff = ((uint32_t)c ^ lsw) * 16u;
            cp_async16(sb + (uint32_t)lrow * 128u + coff,           arow + c * 8);
            cp_async16(sb + A_BYTES + (uint32_t)lrow * 128u + coff, brow + c * 8);
        }
        cp_commit();
    };

    issue_loads(0); issue_loads(1);

    for (int kt = 0; kt < NT; kt++) {
        if (kt < NT - 1) cp_wait<1>();
        else             cp_wait<0>();
        __syncthreads();

        if (kt + NS - 1 < NT) issue_loads(kt + NS - 1);

        const uint32_t sA = base + (uint32_t)(kt % NS) * STAGE_BYTES;
        const uint32_t sB = sA + A_BYTES;
        const uint32_t tof = (uint32_t)t4 * 16u;

        #pragma unroll
        for (int i = 0; i < 2; i++) {
            const uint32_t ie = ((uint32_t)i ^ gpar) * 64u;

            uint32_t B[4][4];
            #pragma unroll
            for (int nt = 0; nt < 4; nt++)
                lds128(B[nt], sB + (uint32_t)(wn + nt * 8 + g) * 128u + ie + tof);

            #pragma unroll
            for (int mh = 0; mh < 2; mh++) {
                uint32_t A0[2][4], A8[2][4];
                #pragma unroll
                for (int m2 = 0; m2 < 2; m2++) {
                    uint32_t ad = sA + (uint32_t)(wm + (mh * 2 + m2) * 16 + g) * 128u + ie + tof;
                    lds128(A0[m2], ad);
                    lds128(A8[m2], ad + 8 * 128);
                }
                #pragma unroll
                for (int s = 0; s < 2; s++)
                    #pragma unroll
                    for (int m2 = 0; m2 < 2; m2++)
                        #pragma unroll
                        for (int nt = 0; nt < 4; nt++)
                            mma_f16(acc[mh * 2 + m2][nt],
                                    A0[m2][2 * s], A8[m2][2 * s],
                                    A0[m2][2 * s + 1], A8[m2][2 * s + 1],
                                    B[nt][2 * s], B[nt][2 * s + 1]);
            }
        }
    }

    #pragma unroll
    for (int mt = 0; mt < 4; mt++) {
        #pragma unroll
        for (int nt = 0; nt < 4; nt++) {
            int m = bm0 + wm + mt * 16 + g;
            int n = bn0 + wn + nt * 8 + t4 * 2;
            *(float2*)&g_V[(size_t)m * 4096 + n]       = make_float2(acc[mt][nt][0], acc[mt][nt][1]);
            *(float2*)&g_V[(size_t)(m + 8) * 4096 + n] = make_float2(acc[mt][nt][2], acc[mt][nt][3]);
        }
    }
}

// ---- Kernel 2: persistent LN + LSTM + LN ------------------------------------
// Params staged once into dynamic smem (float4 index):
//   [0,1024) bias | [1024,2048) gamma_ifgo | [2048,3072) beta_ifgo
//   [3072,3328) gamma_c | [3328,3584) beta_c

__device__ __forceinline__ float sigm(float v) {
    return __fdividef(1.f, 1.f + __expf(-v));
}
__device__ __forceinline__ float tanh_f(float v) {
    return fmaf(2.f, sigm(2.f * v), -1.f);
}
__device__ __forceinline__ float sum4(float4 v) { return v.x + v.y + v.z + v.w; }
__device__ __forceinline__ float sq4(float4 v) {
    return v.x * v.x + v.y * v.y + v.z * v.z + v.w * v.w;
}

__global__ __launch_bounds__(128)
void ln_lstm(const float* __restrict__ cin,
             const float* __restrict__ b_ih,
             const float* __restrict__ gamma_ifgo, const float* __restrict__ beta_ifgo,
             const float* __restrict__ gamma_c,    const float* __restrict__ beta_c,
             float* __restrict__ out) {
    extern __shared__ float4 prm[];       // 3584 float4
    __shared__ float red[4][8];
    __shared__ float red2[4][2];

    const int tid = threadIdx.x;          // 0..127; owns 8 H-elems per row
    const int w   = tid >> 5;

    // cooperative param stage
    for (int i = tid; i < 3584; i += 128) {
        float4 v;
        if (i < 1024)      v = ((const float4*)b_ih)[i];
        else if (i < 2048) v = ((const float4*)gamma_ifgo)[i - 1024];
        else if (i < 3072) v = ((const float4*)beta_ifgo)[i - 2048];
        else if (i < 3328) v = ((const float4*)gamma_c)[i - 3072];
        else               v = ((const float4*)beta_c)[i - 3328];
        prm[i] = v;
    }
    __syncthreads();

    auto load_row = [&](int b, float4* v8, float4* c2v) {
        const float4* vb = (const float4*)(g_V + (size_t)b * 4096);
        #pragma unroll
        for (int g = 0; g < 4; g++) {
            v8[g * 2]     = vb[g * 256 + tid * 2];
            v8[g * 2 + 1] = vb[g * 256 + tid * 2 + 1];
        }
        const float4* cb = (const float4*)(cin + (size_t)b * 1024);
        c2v[0] = cb[tid * 2];
        c2v[1] = cb[tid * 2 + 1];
    };

    float4 vb_[8], cb_[2];
    int b0 = blockIdx.x;
    if (b0 < 4096) load_row(b0, vb_, cb_);

    for (int b = b0; b < 4096; b += LN_BLOCKS) {
        float4 vn[8], cn[2];
        const int nb = b + LN_BLOCKS;
        if (nb < 4096) load_row(nb, vn, cn);   // prefetch next row

        // gate LN stats
        float4 wv[4][2];
        float  s[4], ss[4];
        #pragma unroll
        for (int g = 0; g < 4; g++) {
            float4 t0 = vb_[g * 2], t1 = vb_[g * 2 + 1];
            float4 q0 = prm[g * 256 + tid * 2];
            float4 q1 = prm[g * 256 + tid * 2 + 1];
            t0.x += q0.x; t0.y += q0.y; t0.z += q0.z; t0.w += q0.w;
            t1.x += q1.x; t1.y += q1.y; t1.z += q1.z; t1.w += q1.w;
            wv[g][0] = t0; wv[g][1] = t1;
            s[g]  = sum4(t0) + sum4(t1);
            ss[g] = sq4(t0) + sq4(t1);
        }
        #pragma unroll
        for (int o = 16; o > 0; o >>= 1) {
            #pragma unroll
            for (int g = 0; g < 4; g++) {
                s[g]  += __shfl_xor_sync(0xffffffffu, s[g],  o);
                ss[g] += __shfl_xor_sync(0xffffffffu, ss[g], o);
            }
        }
        if ((tid & 31) == 0) {
            #pragma unroll
            for (int g = 0; g < 4; g++) { red[w][g * 2] = s[g]; red[w][g * 2 + 1] = ss[g]; }
        }
        __syncthreads();

        float4 gate[4][2];
        #pragma unroll
        for (int g = 0; g < 4; g++) {
            float S  = red[0][g * 2]     + red[1][g * 2]     + red[2][g * 2]     + red[3][g * 2];
            float SS = red[0][g * 2 + 1] + red[1][g * 2 + 1] + red[2][g * 2 + 1] + red[3][g * 2 + 1];
            float mean = S * (1.f / 1024.f);
            float var  = fmaxf(SS - S * mean, 0.f) * (1.f / 1023.f);
            float inv  = 1.f / (sqrtf(var) + 1e-6f);
            #pragma unroll
            for (int q = 0; q < 2; q++) {
                float4 ga = prm[1024 + g * 256 + tid * 2 + q];
                float4 be = prm[2048 + g * 256 + tid * 2 + q];
                float4 t  = wv[g][q];
                gate[g][q].x = ga.x * (t.x - mean) * inv + be.x;
                gate[g][q].y = ga.y * (t.y - mean) * inv + be.y;
                gate[g][q].z = ga.z * (t.z - mean) * inv + be.z;
                gate[g][q].w = ga.w * (t.w - mean) * inv + be.w;
            }
        }

        float4 cc[2];
        float s2 = 0.f, ss2 = 0.f;
        #pragma unroll
        for (int q = 0; q < 2; q++) {
            float4 ci = cb_[q];
            float4 v;
            v.x = ci.x * sigm(gate[1][q].x + 1.f) + sigm(gate[0][q].x) * tanh_f(gate[2][q].x);
            v.y = ci.y * sigm(gate[1][q].y + 1.f) + sigm(gate[0][q].y) * tanh_f(gate[2][q].y);
            v.z = ci.z * sigm(gate[1][q].z + 1.f) + sigm(gate[0][q].z) * tanh_f(gate[2][q].z);
            v.w = ci.w * sigm(gate[1][q].w + 1.f) + sigm(gate[0][q].w) * tanh_f(gate[2][q].w);
            cc[q] = v;
            s2  += sum4(v);
            ss2 += sq4(v);
        }
        #pragma unroll
        for (int o = 16; o > 0; o >>= 1) {
            s2  += __shfl_xor_sync(0xffffffffu, s2,  o);
            ss2 += __shfl_xor_sync(0xffffffffu, ss2, o);
        }
        if ((tid & 31) == 0) { red2[w][0] = s2; red2[w][1] = ss2; }
        __syncthreads();
        float S  = red2[0][0] + red2[1][0] + red2[2][0] + red2[3][0];
        float SS = red2[0][1] + red2[1][1] + red2[2][1] + red2[3][1];
        float mean = S * (1.f / 1024.f);
        float var  = fmaxf(SS - S * mean, 0.f) * (1.f / 1023.f);
        float inv  = 1.f / (sqrtf(var) + 1e-6f);

        #pragma unroll
        for (int q = 0; q < 2; q++) {
            float4 gc = prm[3072 + tid * 2 + q];
            float4 bc = prm[3328 + tid * 2 + q];
            float4 nc, nh;
            nc.x = gc.x * (cc[q].x - mean) * inv + bc.x;  nh.x = tanh_f(nc.x) * sigm(gate[3][q].x);
            nc.y = gc.y * (cc[q].y - mean) * inv + bc.y;  nh.y = tanh_f(nc.y) * sigm(gate[3][q].y);
            nc.z = gc.z * (cc[q].z - mean) * inv + bc.z;  nh.z = tanh_f(nc.z) * sigm(gate[3][q].z);
            nc.w = gc.w * (cc[q].w - mean) * inv + bc.w;  nh.w = tanh_f(nc.w) * sigm(gate[3][q].w);
            ((float4*)out)[(size_t)b * 256 + tid * 2 + q]                      = nh;
            ((float4*)out)[(size_t)4096 * 256 + (size_t)b * 256 + tid * 2 + q] = nc;
        }

        // rotate prefetched row in
        #pragma unroll
        for (int i = 0; i < 8; i++) vb_[i] = vn[i];
        cb_[0] = cn[0]; cb_[1] = cn[1];
    }
}

// ---- launch ----------------------------------------------------------------

extern "C" void kernel_launch(void* const* d_in, const int* in_sizes, int n_in,
                              void* d_out, int out_size) {
    const float* x     = (const float*)d_in[0];
    const float* h     = (const float*)d_in[1];
    const float* c     = (const float*)d_in[2];
    const float* Wih   = (const float*)d_in[3];
    const float* bih   = (const float*)d_in[4];
    const float* Whh   = (const float*)d_in[5];
    const float* gifgo = (const float*)d_in[6];
    const float* bifgo = (const float*)d_in[7];
    const float* gc    = (const float*)d_in[8];
    const float* bc    = (const float*)d_in[9];
    float* out = (float*)d_out;

    __half *gA, *gW;
    cudaGetSymbolAddress((void**)&gA, g_A);
    cudaGetSymbolAddress((void**)&gW, g_W);

    cudaFuncSetAttribute(gemm_f16, cudaFuncAttributeMaxDynamicSharedMemorySize, SMEM_SZ);
    cudaFuncSetAttribute(ln_lstm, cudaFuncAttributeMaxDynamicSharedMemorySize, LN_SMEM);

    tohalf<<<8192, 256>>>(x, h, Wih, Whh);
    dim3 grid(4096 / BN, 4096 / BM);            // 32 x 32
    gemm_f16<<<grid, 256, SMEM_SZ>>>(gA, gW);
    ln_lstm<<<LN_BLOCKS, 128, LN_SMEM>>>(c, bih, gifgo, bifgo, gc, bc, out);
}

// round 17
// speedup vs baseline: 1.0955x; 1.0520x over previous
#include <cuda_runtime.h>
#include <cuda_fp16.h>
#include <cstdint>

// ---------------------------------------------------------------------------
// Fused LayerNorm-LSTM cell, sm_100 legacy tensor path.  (R14 + L2-order flip)
//   Kernel 0: convert x,h -> g_A, Wih,Whh -> g_W (fp16, k-permuted).
//   Kernel 1: v = A @ W^T via mma.sync.m16n8k16.f16 -> g_V f32 (R14 exact).
//   Kernel 2: 4x LN + LSTM + LN; rows processed DESCENDING to match the
//             GEMM's write order (freshest g_V rows read first -> L2 hits).
// ---------------------------------------------------------------------------

#define BM 128
#define BN 128
#define BKH 64                          // k halfs per stage (128 B per row)
#define NS 3
#define NT 32                           // 2048 / 64
#define A_BYTES (BM * 128)              // 16384
#define STAGE_BYTES ((BM + BN) * 128)   // 32768
#define SMEM_SZ (NS * STAGE_BYTES + 1024)   // 99328

__device__ float  g_V[4096u * 4096u];   // 64 MB pre-LN gate activations
__device__ __half g_A[4096u * 2048u];   // 16 MB fp16 [x|h], k-permuted
__device__ __half g_W[4096u * 2048u];   // 16 MB fp16 [Wih|Whh], k-permuted

// ---- helpers ---------------------------------------------------------------

__device__ __forceinline__ uint32_t s2u(const void* p) {
    return (uint32_t)__cvta_generic_to_shared(p);
}
__device__ __forceinline__ void cp_async16(uint32_t dst, const void* src) {
    asm volatile("cp.async.cg.shared.global [%0], [%1], 16;\n" :: "r"(dst), "l"(src));
}
__device__ __forceinline__ void cp_commit() {
    asm volatile("cp.async.commit_group;\n" ::: "memory");
}
template <int N> __device__ __forceinline__ void cp_wait() {
    asm volatile("cp.async.wait_group %0;\n" :: "n"(N) : "memory");
}
__device__ __forceinline__ void lds128(uint32_t* v, uint32_t a) {
    asm volatile("ld.shared.v4.b32 {%0,%1,%2,%3}, [%4];"
                 : "=r"(v[0]), "=r"(v[1]), "=r"(v[2]), "=r"(v[3]) : "r"(a));
}
__device__ __forceinline__ void mma_f16(float* d, uint32_t a0, uint32_t a1,
                                        uint32_t a2, uint32_t a3,
                                        uint32_t b0, uint32_t b1) {
    asm volatile(
        "mma.sync.aligned.m16n8k16.row.col.f32.f16.f16.f32 "
        "{%0,%1,%2,%3}, {%4,%5,%6,%7}, {%8,%9}, {%0,%1,%2,%3};\n"
        : "+f"(d[0]), "+f"(d[1]), "+f"(d[2]), "+f"(d[3])
        : "r"(a0), "r"(a1), "r"(a2), "r"(a3), "r"(b0), "r"(b1));
}

// ---- Kernel 0: fp16 convert + k-permute, 1 thread per 16B output -----------

__global__ __launch_bounds__(256)
void tohalf(const float* __restrict__ x, const float* __restrict__ h,
            const float* __restrict__ Wih, const float* __restrict__ Whh) {
    const uint32_t q = blockIdx.x * 256u + threadIdx.x;     // 0 .. 2M-1
    const uint32_t tensor = q >> 20;                        // 0=A, 1=W
    const uint32_t r = q & 0xFFFFFu;
    const uint32_t blk = r >> 2;
    const uint32_t i = r & 3u;
    const uint32_t row = blk >> 6;
    const uint32_t chunk = blk & 63u;

    const float* src;
    __half* dst;
    if (tensor == 0) {
        src = (chunk < 32u) ? x + (size_t)row * 1024 + chunk * 32
                            : h + (size_t)row * 1024 + (chunk - 32u) * 32;
        dst = g_A + (size_t)row * 2048 + chunk * 32;
    } else {
        src = (chunk < 32u) ? Wih + (size_t)row * 1024 + chunk * 32
                            : Whh + (size_t)row * 1024 + (chunk - 32u) * 32;
        dst = g_W + (size_t)row * 2048 + chunk * 32;
    }

    const float2* p = (const float2*)src + i;
    float2 a = p[0], b = p[4], c2 = p[8], d = p[12];
    union { __half2 h2[4]; uint4 u; } o;
    o.h2[0] = __float22half2_rn(a);
    o.h2[1] = __float22half2_rn(b);
    o.h2[2] = __float22half2_rn(c2);
    o.h2[3] = __float22half2_rn(d);
    ((uint4*)dst)[i] = o.u;
}

// ---- Kernel 1: fp16 GEMM, 128x128 tile, 2 CTAs/SM (R14 exact) ---------------

__global__ __launch_bounds__(256, 2)
void gemm_f16(const __half* __restrict__ gA, const __half* __restrict__ gW) {
    extern __shared__ float dsm[];
    const uint32_t dyn0 = s2u(dsm);
    const uint32_t base = (dyn0 + 1023u) & ~1023u;

    const int tid  = threadIdx.x;
    const int warp = tid >> 5;
    const int lane = tid & 31;
    const int g    = lane >> 2;               // 0..7
    const int t4   = lane & 3;                // 0..3
    const int wm = (warp & 1) * 64;           // 64x32 warp tile
    const int wn = (warp >> 1) * 32;
    const int bm0 = blockIdx.y * BM;
    const int bn0 = blockIdx.x * BN;
    const uint32_t gpar = (uint32_t)(g & 1);

    float acc[4][4][4];
    #pragma unroll
    for (int i = 0; i < 4; i++)
        #pragma unroll
        for (int j = 0; j < 4; j++)
            #pragma unroll
            for (int k = 0; k < 4; k++) acc[i][j][k] = 0.f;

    const int lrow = tid >> 1;
    const int lc0  = (tid & 1) * 4;
    const uint32_t lsw = (uint32_t)(lrow & 1) << 2;

    auto issue_loads = [&](int kt) {
        const uint32_t sb = base + (uint32_t)(kt % NS) * STAGE_BYTES;
        const __half* arow = gA + (size_t)(bm0 + lrow) * 2048 + kt * BKH;
        const __half* brow = gW + (size_t)(bn0 + lrow) * 2048 + kt * BKH;
        #pragma unroll
        for (int j = 0; j < 4; j++) {
            int c = lc0 + j;
            uint32_t coff = ((uint32_t)c ^ lsw) * 16u;
            cp_async16(sb + (uint32_t)lrow * 128u + coff,           arow + c * 8);
            cp_async16(sb + A_BYTES + (uint32_t)lrow * 128u + coff, brow + c * 8);
        }
        cp_commit();
    };

    issue_loads(0); issue_loads(1);

    for (int kt = 0; kt < NT; kt++) {
        if (kt < NT - 1) cp_wait<1>();
        else             cp_wait<0>();
        __syncthreads();

        if (kt + NS - 1 < NT) issue_loads(kt + NS - 1);

        const uint32_t sA = base + (uint32_t)(kt % NS) * STAGE_BYTES;
        const uint32_t sB = sA + A_BYTES;
        const uint32_t tof = (uint32_t)t4 * 16u;

        #pragma unroll
        for (int i = 0; i < 2; i++) {
            const uint32_t ie = ((uint32_t)i ^ gpar) * 64u;

            uint32_t B[4][4];
            #pragma unroll
            for (int nt = 0; nt < 4; nt++)
                lds128(B[nt], sB + (uint32_t)(wn + nt * 8 + g) * 128u + ie + tof);

            #pragma unroll
            for (int mh = 0; mh < 2; mh++) {
                uint32_t A0[2][4], A8[2][4];
                #pragma unroll
                for (int m2 = 0; m2 < 2; m2++) {
                    uint32_t ad = sA + (uint32_t)(wm + (mh * 2 + m2) * 16 + g) * 128u + ie + tof;
                    lds128(A0[m2], ad);
                    lds128(A8[m2], ad + 8 * 128);
                }
                #pragma unroll
                for (int s = 0; s < 2; s++)
                    #pragma unroll
                    for (int m2 = 0; m2 < 2; m2++)
                        #pragma unroll
                        for (int nt = 0; nt < 4; nt++)
                            mma_f16(acc[mh * 2 + m2][nt],
                                    A0[m2][2 * s], A8[m2][2 * s],
                                    A0[m2][2 * s + 1], A8[m2][2 * s + 1],
                                    B[nt][2 * s], B[nt][2 * s + 1]);
            }
        }
    }

    #pragma unroll
    for (int mt = 0; mt < 4; mt++) {
        #pragma unroll
        for (int nt = 0; nt < 4; nt++) {
            int m = bm0 + wm + mt * 16 + g;
            int n = bn0 + wn + nt * 8 + t4 * 2;
            *(float2*)&g_V[(size_t)m * 4096 + n]       = make_float2(acc[mt][nt][0], acc[mt][nt][1]);
            *(float2*)&g_V[(size_t)(m + 8) * 4096 + n] = make_float2(acc[mt][nt][2], acc[mt][nt][3]);
        }
    }
}

// ---- Kernel 2: LN + LSTM + LN, 128 threads x 8 elems, descending rows -------

__device__ __forceinline__ float sigm(float v) {
    return __fdividef(1.f, 1.f + __expf(-v));
}
__device__ __forceinline__ float tanh_f(float v) {
    return fmaf(2.f, sigm(2.f * v), -1.f);
}
__device__ __forceinline__ float sum4(float4 v) { return v.x + v.y + v.z + v.w; }
__device__ __forceinline__ float sq4(float4 v) {
    return v.x * v.x + v.y * v.y + v.z * v.z + v.w * v.w;
}

__global__ __launch_bounds__(128)
void ln_lstm(const float* __restrict__ c,
             const float* __restrict__ b_ih,
             const float* __restrict__ gamma_ifgo, const float* __restrict__ beta_ifgo,
             const float* __restrict__ gamma_c,    const float* __restrict__ beta_c,
             float* __restrict__ out) {
    __shared__ float red[4][8];
    __shared__ float red2[4][2];

    const int b   = 4095 - blockIdx.x;      // descending: freshest g_V rows first
    const int tid = threadIdx.x;            // 0..127; owns 8 H-elems
    const int w   = tid >> 5;

    const float4* vb   = (const float4*)(g_V + (size_t)b * 4096);
    const float4* bih4 = (const float4*)b_ih;

    float4 wv[4][2];
    float  s[4], ss[4];
    #pragma unroll
    for (int g = 0; g < 4; g++) {
        float4 t0 = vb[g * 256 + tid * 2];
        float4 t1 = vb[g * 256 + tid * 2 + 1];
        float4 b0 = bih4[g * 256 + tid * 2];
        float4 b1 = bih4[g * 256 + tid * 2 + 1];
        t0.x += b0.x; t0.y += b0.y; t0.z += b0.z; t0.w += b0.w;
        t1.x += b1.x; t1.y += b1.y; t1.z += b1.z; t1.w += b1.w;
        wv[g][0] = t0; wv[g][1] = t1;
        s[g]  = sum4(t0) + sum4(t1);
        ss[g] = sq4(t0) + sq4(t1);
    }
    #pragma unroll
    for (int o = 16; o > 0; o >>= 1) {
        #pragma unroll
        for (int g = 0; g < 4; g++) {
            s[g]  += __shfl_xor_sync(0xffffffffu, s[g],  o);
            ss[g] += __shfl_xor_sync(0xffffffffu, ss[g], o);
        }
    }
    if ((tid & 31) == 0) {
        #pragma unroll
        for (int g = 0; g < 4; g++) { red[w][g * 2] = s[g]; red[w][g * 2 + 1] = ss[g]; }
    }
    __syncthreads();

    float4 gate[4][2];
    #pragma unroll
    for (int g = 0; g < 4; g++) {
        float S  = red[0][g * 2]     + red[1][g * 2]     + red[2][g * 2]     + red[3][g * 2];
        float SS = red[0][g * 2 + 1] + red[1][g * 2 + 1] + red[2][g * 2 + 1] + red[3][g * 2 + 1];
        float mean = S * (1.f / 1024.f);
        float var  = fmaxf(SS - S * mean, 0.f) * (1.f / 1023.f);
        float inv  = 1.f / (sqrtf(var) + 1e-6f);
        #pragma unroll
        for (int q = 0; q < 2; q++) {
            float4 ga = ((const float4*)gamma_ifgo)[g * 256 + tid * 2 + q];
            float4 be = ((const float4*)beta_ifgo)[g * 256 + tid * 2 + q];
            float4 t  = wv[g][q];
            gate[g][q].x = ga.x * (t.x - mean) * inv + be.x;
            gate[g][q].y = ga.y * (t.y - mean) * inv + be.y;
            gate[g][q].z = ga.z * (t.z - mean) * inv + be.z;
            gate[g][q].w = ga.w * (t.w - mean) * inv + be.w;
        }
    }

    float4 cc[2];
    float s2 = 0.f, ss2 = 0.f;
    #pragma unroll
    for (int q = 0; q < 2; q++) {
        float4 ci = ((const float4*)(c + (size_t)b * 1024))[tid * 2 + q];
        float4 v;
        v.x = ci.x * sigm(gate[1][q].x + 1.f) + sigm(gate[0][q].x) * tanh_f(gate[2][q].x);
        v.y = ci.y * sigm(gate[1][q].y + 1.f) + sigm(gate[0][q].y) * tanh_f(gate[2][q].y);
        v.z = ci.z * sigm(gate[1][q].z + 1.f) + sigm(gate[0][q].z) * tanh_f(gate[2][q].z);
        v.w = ci.w * sigm(gate[1][q].w + 1.f) + sigm(gate[0][q].w) * tanh_f(gate[2][q].w);
        cc[q] = v;
        s2  += sum4(v);
        ss2 += sq4(v);
    }
    #pragma unroll
    for (int o = 16; o > 0; o >>= 1) {
        s2  += __shfl_xor_sync(0xffffffffu, s2,  o);
        ss2 += __shfl_xor_sync(0xffffffffu, ss2, o);
    }
    if ((tid & 31) == 0) { red2[w][0] = s2; red2[w][1] = ss2; }
    __syncthreads();
    float S  = red2[0][0] + red2[1][0] + red2[2][0] + red2[3][0];
    float SS = red2[0][1] + red2[1][1] + red2[2][1] + red2[3][1];
    float mean = S * (1.f / 1024.f);
    float var  = fmaxf(SS - S * mean, 0.f) * (1.f / 1023.f);
    float inv  = 1.f / (sqrtf(var) + 1e-6f);

    #pragma unroll
    for (int q = 0; q < 2; q++) {
        float4 gc = ((const float4*)gamma_c)[tid * 2 + q];
        float4 bc = ((const float4*)beta_c)[tid * 2 + q];
        float4 nc, nh;
        nc.x = gc.x * (cc[q].x - mean) * inv + bc.x;  nh.x = tanh_f(nc.x) * sigm(gate[3][q].x);
        nc.y = gc.y * (cc[q].y - mean) * inv + bc.y;  nh.y = tanh_f(nc.y) * sigm(gate[3][q].y);
        nc.z = gc.z * (cc[q].z - mean) * inv + bc.z;  nh.z = tanh_f(nc.z) * sigm(gate[3][q].z);
        nc.w = gc.w * (cc[q].w - mean) * inv + bc.w;  nh.w = tanh_f(nc.w) * sigm(gate[3][q].w);
        ((float4*)out)[(size_t)b * 256 + tid * 2 + q]                      = nh;
        ((float4*)out)[(size_t)4096 * 256 + (size_t)b * 256 + tid * 2 + q] = nc;
    }
}

// ---- launch ----------------------------------------------------------------

extern "C" void kernel_launch(void* const* d_in, const int* in_sizes, int n_in,
                              void* d_out, int out_size) {
    const float* x     = (const float*)d_in[0];
    const float* h     = (const float*)d_in[1];
    const float* c     = (const float*)d_in[2];
    const float* Wih   = (const float*)d_in[3];
    const float* bih   = (const float*)d_in[4];
    const float* Whh   = (const float*)d_in[5];
    const float* gifgo = (const float*)d_in[6];
    const float* bifgo = (const float*)d_in[7];
    const float* gc    = (const float*)d_in[8];
    const float* bc    = (const float*)d_in[9];
    float* out = (float*)d_out;

    __half *gA, *gW;
    cudaGetSymbolAddress((void**)&gA, g_A);
    cudaGetSymbolAddress((void**)&gW, g_W);

    cudaFuncSetAttribute(gemm_f16, cudaFuncAttributeMaxDynamicSharedMemorySize, SMEM_SZ);

    tohalf<<<8192, 256>>>(x, h, Wih, Whh);
    dim3 grid(4096 / BN, 4096 / BM);            // 32 x 32
    gemm_f16<<<grid, 256, SMEM_SZ>>>(gA, gW);
    ln_lstm<<<4096, 128>>>(c, bih, gifgo, bifgo, gc, bc, out);
}